// round 9
// baseline (speedup 1.0000x reference)
#include <cuda_runtime.h>
#include <cuda_bf16.h>

// Problem constants (fixed by setup_inputs):
//   x: [B=2, C=3, D=128, H=160, W=160] float32, num_steps = 6
#define BB    2
#define DD    128
#define HH    160
#define WW    160
#define PLANE (DD * HH * WW)          // 3,276,800 voxels per (batch) volume
#define NVOX  (BB * PLANE)

// Interleaved ping-pong scratch: float4 per voxel = (flow_d, flow_h, flow_w, 0).
// Batches processed sequentially so the active set (~105 MB) mostly fits L2.
__device__ float4 g_bufA[NVOX];
__device__ float4 g_bufB[NVOX];

__device__ __forceinline__ int clampi(int v, int lo, int hi) {
    return min(max(v, lo), hi);
}

// ---------------------------------------------------------------------------
// Step 1 (one batch): planar x -> interleaved. Scale fused (s = 1/64, pow2).
// ---------------------------------------------------------------------------
__global__ __launch_bounds__(256) void sq_first(const float* __restrict__ sb,
                                                float4* __restrict__ db,
                                                float s) {
    const int W4 = WW / 4;
    int idx = blockIdx.x * blockDim.x + threadIdx.x;   // grid covers DD*HH*W4
    int w4 = idx % W4;
    int t  = idx / W4;
    int h  = t % HH;
    int d  = t / HH;

    const int p = (d * HH + h) * WW + w4 * 4;

    float4 f0 = *reinterpret_cast<const float4*>(sb + p);              // d-flow
    float4 f1 = *reinterpret_cast<const float4*>(sb + p + PLANE);      // h-flow
    float4 f2 = *reinterpret_cast<const float4*>(sb + p + 2 * PLANE);  // w-flow

    f0.x *= s; f0.y *= s; f0.z *= s; f0.w *= s;
    f1.x *= s; f1.y *= s; f1.z *= s; f1.w *= s;
    f2.x *= s; f2.y *= s; f2.z *= s; f2.w *= s;

    float fd[4] = {f0.x, f0.y, f0.z, f0.w};
    float fh[4] = {f1.x, f1.y, f1.z, f1.w};
    float fw[4] = {f2.x, f2.y, f2.z, f2.w};

#pragma unroll
    for (int j = 0; j < 4; ++j) {
        int id = clampi(__float2int_rn((float)d + fd[j]), 0, DD - 1);
        int ih = clampi(__float2int_rn((float)h + fh[j]), 0, HH - 1);
        int iw = clampi(__float2int_rn((float)(w4 * 4 + j) + fw[j]), 0, WW - 1);
        const int q = (id * HH + ih) * WW + iw;
        float gd = s * sb[q];
        float gh = s * sb[q + PLANE];
        float gw = s * sb[q + 2 * PLANE];
        db[p + j] = make_float4(fd[j] + gd, fh[j] + gh, fw[j] + gw, 0.0f);
    }
}

// ---------------------------------------------------------------------------
// Steps 2..5 (one batch): interleaved -> interleaved.
// 4 voxels/thread, warp-contiguous: v = base + lane + {0,32,64,96}.
// All 4 stream loads batched, then 4 independent gathers in flight (MLP=4).
// PLANE = 3,276,800 = 3200 blocks * 1024 voxels exactly.
// ---------------------------------------------------------------------------
__global__ __launch_bounds__(256) void sq_mid(const float4* __restrict__ src,
                                              float4* __restrict__ dst) {
    const int lane = threadIdx.x & 31;
    const int warp = threadIdx.x >> 5;
    const int base = blockIdx.x * 1024 + warp * 128 + lane;  // in [0, PLANE)

    // Batch the 4 coalesced stream loads up front (independent LDG.128s).
    float4 a[4];
#pragma unroll
    for (int j = 0; j < 4; ++j) a[j] = src[base + j * 32];

    // Index math for all 4, then 4 independent gathers.
    int q[4];
#pragma unroll
    for (int j = 0; j < 4; ++j) {
        const int v = base + j * 32;
        int w = v % WW;  int t = v / WW;
        int h = t % HH;  int d = t / HH;
        int id = clampi(__float2int_rn((float)d + a[j].x), 0, DD - 1);
        int ih = clampi(__float2int_rn((float)h + a[j].y), 0, HH - 1);
        int iw = clampi(__float2int_rn((float)w + a[j].z), 0, WW - 1);
        q[j] = (id * HH + ih) * WW + iw;
    }

    float4 g[4];
#pragma unroll
    for (int j = 0; j < 4; ++j) g[j] = src[q[j]];

#pragma unroll
    for (int j = 0; j < 4; ++j) {
        dst[base + j * 32] =
            make_float4(a[j].x + g[j].x, a[j].y + g[j].y, a[j].z + g[j].z, 0.0f);
    }
}

// ---------------------------------------------------------------------------
// Step 6 (one batch): interleaved -> planar out. 4 voxels/thread, coalesced
// planar float4 stores per channel.
// ---------------------------------------------------------------------------
__global__ __launch_bounds__(256) void sq_last(const float4* __restrict__ sb,
                                               float* __restrict__ ob) {
    const int W4 = WW / 4;
    int idx = blockIdx.x * blockDim.x + threadIdx.x;
    int w4 = idx % W4;
    int t  = idx / W4;
    int h  = t % HH;
    int d  = t / HH;

    const int p = (d * HH + h) * WW + w4 * 4;

    float4 a[4];
#pragma unroll
    for (int j = 0; j < 4; ++j) a[j] = sb[p + j];

    float o0[4], o1[4], o2[4];
#pragma unroll
    for (int j = 0; j < 4; ++j) {
        int id = clampi(__float2int_rn((float)d + a[j].x), 0, DD - 1);
        int ih = clampi(__float2int_rn((float)h + a[j].y), 0, HH - 1);
        int iw = clampi(__float2int_rn((float)(w4 * 4 + j) + a[j].z), 0, WW - 1);
        float4 g = sb[(id * HH + ih) * WW + iw];
        o0[j] = a[j].x + g.x;
        o1[j] = a[j].y + g.y;
        o2[j] = a[j].z + g.z;
    }

    *reinterpret_cast<float4*>(ob + p)             = make_float4(o0[0], o0[1], o0[2], o0[3]);
    *reinterpret_cast<float4*>(ob + p + PLANE)     = make_float4(o1[0], o1[1], o1[2], o1[3]);
    *reinterpret_cast<float4*>(ob + p + 2 * PLANE) = make_float4(o2[0], o2[1], o2[2], o2[3]);
}

extern "C" void kernel_launch(void* const* d_in, const int* in_sizes, int n_in,
                              void* d_out, int out_size) {
    const float* x   = (const float*)d_in[0];
    float*       out = (float*)d_out;

    float4 *A = nullptr, *B = nullptr;
    cudaGetSymbolAddress((void**)&A, g_bufA);
    cudaGetSymbolAddress((void**)&B, g_bufB);

    const int tpb  = 256;
    const int blkQ = (DD * HH * (WW / 4)) / tpb;   // 3200 blocks
    const int blkM = PLANE / 1024;                 // 3200, exact

    const float s0 = 1.0f / 64.0f;                 // 1 / 2^num_steps (num_steps = 6)

    // Process each batch sample fully before the next: keeps the per-batch
    // ping-pong working set (~105 MB) mostly resident in the 126 MB L2.
    for (int b = 0; b < BB; ++b) {
        const float* xb = x   + (size_t)b * 3 * PLANE;
        float*       ob = out + (size_t)b * 3 * PLANE;
        float4*      Ab = A   + (size_t)b * PLANE;
        float4*      Bb = B   + (size_t)b * PLANE;

        sq_first<<<blkQ, tpb>>>(xb, Ab, s0);   // step 1: planar -> interleaved
        sq_mid  <<<blkM, tpb>>>(Ab, Bb);       // step 2
        sq_mid  <<<blkM, tpb>>>(Bb, Ab);       // step 3
        sq_mid  <<<blkM, tpb>>>(Ab, Bb);       // step 4
        sq_mid  <<<blkM, tpb>>>(Bb, Ab);       // step 5
        sq_last <<<blkQ, tpb>>>(Ab, ob);       // step 6: interleaved -> planar
    }
}

// round 10
// speedup vs baseline: 1.0527x; 1.0527x over previous
#include <cuda_runtime.h>
#include <cuda_bf16.h>

// Problem constants (fixed by setup_inputs):
//   x: [B=2, C=3, D=128, H=160, W=160] float32, num_steps = 6
#define BB    2
#define DD    128
#define HH    160
#define WW    160
#define PLANE (DD * HH * WW)          // 3,276,800 voxels per (batch) volume
#define NVOX  (BB * PLANE)

// Interleaved ping-pong scratch: float4 per voxel = (flow_d, flow_h, flow_w, 0).
// Batches processed sequentially so the active set (~105 MB) mostly fits L2.
__device__ float4 g_bufA[NVOX];
__device__ float4 g_bufB[NVOX];

__device__ __forceinline__ int clampi(int v, int lo, int hi) {
    return min(max(v, lo), hi);
}

// ---------------------------------------------------------------------------
// Fused steps 1+2 (one batch): planar x -> interleaved v2.
//   v0(y)  = s * x(y)                       (s = 1/64, exact pow2)
//   q0(y)  = clamp(rn(y + v0(y)))
//   v1(y)  = v0(y) + v0(q0(y))
//   q1     = clamp(rn(p + v1(p)))
//   v2(p)  = v1(p) + v1(q1)                 (v1(q1) recomputed, bitwise same)
// All gathers are near-identity (|v| <= ~1.5 voxels) -> warp-coalesced.
// ---------------------------------------------------------------------------
__global__ __launch_bounds__(256) void sq_fuse12(const float* __restrict__ xb,
                                                 float4* __restrict__ db,
                                                 float s) {
    const int W4 = WW / 4;
    int idx = blockIdx.x * blockDim.x + threadIdx.x;   // grid covers DD*HH*W4
    int w4 = idx % W4;
    int t  = idx / W4;
    int h  = t % HH;
    int d  = t / HH;

    const int p = (d * HH + h) * WW + w4 * 4;

    float4 f0 = *reinterpret_cast<const float4*>(xb + p);              // d-flow
    float4 f1 = *reinterpret_cast<const float4*>(xb + p + PLANE);      // h-flow
    float4 f2 = *reinterpret_cast<const float4*>(xb + p + 2 * PLANE);  // w-flow

    float v0d[4] = {s * f0.x, s * f0.y, s * f0.z, s * f0.w};
    float v0h[4] = {s * f1.x, s * f1.y, s * f1.z, s * f1.w};
    float v0w[4] = {s * f2.x, s * f2.y, s * f2.z, s * f2.w};

#pragma unroll
    for (int j = 0; j < 4; ++j) {
        const int w = w4 * 4 + j;

        // ---- v1 at p ----
        int a_d = clampi(__float2int_rn((float)d + v0d[j]), 0, DD - 1);
        int a_h = clampi(__float2int_rn((float)h + v0h[j]), 0, HH - 1);
        int a_w = clampi(__float2int_rn((float)w + v0w[j]), 0, WW - 1);
        int qa = (a_d * HH + a_h) * WW + a_w;                 // q0(p)
        float v1pd = v0d[j] + s * xb[qa];
        float v1ph = v0h[j] + s * xb[qa + PLANE];
        float v1pw = v0w[j] + s * xb[qa + 2 * PLANE];

        // ---- q1 = clamp(rn(p + v1(p))) ----
        int b_d = clampi(__float2int_rn((float)d + v1pd), 0, DD - 1);
        int b_h = clampi(__float2int_rn((float)h + v1ph), 0, HH - 1);
        int b_w = clampi(__float2int_rn((float)w + v1pw), 0, WW - 1);
        int qb = (b_d * HH + b_h) * WW + b_w;                 // q1

        // ---- v1 at q1 (recomputed exactly as pass 1 would have stored) ----
        float u0d = s * xb[qb];
        float u0h = s * xb[qb + PLANE];
        float u0w = s * xb[qb + 2 * PLANE];
        int c_d = clampi(__float2int_rn((float)b_d + u0d), 0, DD - 1);
        int c_h = clampi(__float2int_rn((float)b_h + u0h), 0, HH - 1);
        int c_w = clampi(__float2int_rn((float)b_w + u0w), 0, WW - 1);
        int qc = (c_d * HH + c_h) * WW + c_w;                 // q0(q1)
        float v1qd = u0d + s * xb[qc];
        float v1qh = u0h + s * xb[qc + PLANE];
        float v1qw = u0w + s * xb[qc + 2 * PLANE];

        // ---- v2(p) = v1(p) + v1(q1) ----
        db[p + j] = make_float4(v1pd + v1qd, v1ph + v1qh, v1pw + v1qw, 0.0f);
    }
}

// ---------------------------------------------------------------------------
// Steps 3..5 (one batch): interleaved -> interleaved.
// 2 voxels/thread, warp-contiguous: v0 = base + lane, v1 = v0 + 32.
// (R3 version: measured at the L2-bytes roofline, 18.4 us.)
// PLANE = 3,276,800 = 6400 blocks * 512 voxels exactly.
// ---------------------------------------------------------------------------
__global__ __launch_bounds__(256) void sq_mid(const float4* __restrict__ src,
                                              float4* __restrict__ dst) {
    const int lane = threadIdx.x & 31;
    const int warp = threadIdx.x >> 5;
    const int v0 = blockIdx.x * 512 + warp * 64 + lane;   // in [0, PLANE)
    const int v1 = v0 + 32;

    float4 a0 = src[v0];
    float4 a1 = src[v1];

    int w0 = v0 % WW;  int t0 = v0 / WW;
    int h0 = t0 % HH;  int d0 = t0 / HH;
    int w1 = v1 % WW;  int t1 = v1 / WW;
    int h1 = t1 % HH;  int d1 = t1 / HH;

    int id0 = clampi(__float2int_rn((float)d0 + a0.x), 0, DD - 1);
    int ih0 = clampi(__float2int_rn((float)h0 + a0.y), 0, HH - 1);
    int iw0 = clampi(__float2int_rn((float)w0 + a0.z), 0, WW - 1);
    int id1 = clampi(__float2int_rn((float)d1 + a1.x), 0, DD - 1);
    int ih1 = clampi(__float2int_rn((float)h1 + a1.y), 0, HH - 1);
    int iw1 = clampi(__float2int_rn((float)w1 + a1.z), 0, WW - 1);

    float4 g0 = src[(id0 * HH + ih0) * WW + iw0];
    float4 g1 = src[(id1 * HH + ih1) * WW + iw1];

    dst[v0] = make_float4(a0.x + g0.x, a0.y + g0.y, a0.z + g0.z, 0.0f);
    dst[v1] = make_float4(a1.x + g1.x, a1.y + g1.y, a1.z + g1.z, 0.0f);
}

// ---------------------------------------------------------------------------
// Step 6 (one batch): interleaved -> planar out. 4 voxels/thread, coalesced
// planar float4 stores per channel.
// ---------------------------------------------------------------------------
__global__ __launch_bounds__(256) void sq_last(const float4* __restrict__ sb,
                                               float* __restrict__ ob) {
    const int W4 = WW / 4;
    int idx = blockIdx.x * blockDim.x + threadIdx.x;
    int w4 = idx % W4;
    int t  = idx / W4;
    int h  = t % HH;
    int d  = t / HH;

    const int p = (d * HH + h) * WW + w4 * 4;

    float o0[4], o1[4], o2[4];
#pragma unroll
    for (int j = 0; j < 4; ++j) {
        float4 a = sb[p + j];
        int id = clampi(__float2int_rn((float)d + a.x), 0, DD - 1);
        int ih = clampi(__float2int_rn((float)h + a.y), 0, HH - 1);
        int iw = clampi(__float2int_rn((float)(w4 * 4 + j) + a.z), 0, WW - 1);
        float4 g = sb[(id * HH + ih) * WW + iw];
        o0[j] = a.x + g.x;
        o1[j] = a.y + g.y;
        o2[j] = a.z + g.z;
    }

    *reinterpret_cast<float4*>(ob + p)             = make_float4(o0[0], o0[1], o0[2], o0[3]);
    *reinterpret_cast<float4*>(ob + p + PLANE)     = make_float4(o1[0], o1[1], o1[2], o1[3]);
    *reinterpret_cast<float4*>(ob + p + 2 * PLANE) = make_float4(o2[0], o2[1], o2[2], o2[3]);
}

extern "C" void kernel_launch(void* const* d_in, const int* in_sizes, int n_in,
                              void* d_out, int out_size) {
    const float* x   = (const float*)d_in[0];
    float*       out = (float*)d_out;

    float4 *A = nullptr, *B = nullptr;
    cudaGetSymbolAddress((void**)&A, g_bufA);
    cudaGetSymbolAddress((void**)&B, g_bufB);

    const int tpb  = 256;
    const int blkQ = (DD * HH * (WW / 4)) / tpb;   // 3200 blocks (4 voxels/thread)
    const int blkM = PLANE / 512;                  // 6400, exact (2 voxels/thread)

    const float s0 = 1.0f / 64.0f;                 // 1 / 2^num_steps (num_steps = 6)

    // Batch-sequential: keeps the per-batch ping-pong working set (~105 MB)
    // mostly resident in the 126 MB L2.
    for (int b = 0; b < BB; ++b) {
        const float* xb = x   + (size_t)b * 3 * PLANE;
        float*       ob = out + (size_t)b * 3 * PLANE;
        float4*      Ab = A   + (size_t)b * PLANE;
        float4*      Bb = B   + (size_t)b * PLANE;

        sq_fuse12<<<blkQ, tpb>>>(xb, Ab, s0);  // steps 1+2 fused: x -> v2
        sq_mid   <<<blkM, tpb>>>(Ab, Bb);      // step 3
        sq_mid   <<<blkM, tpb>>>(Bb, Ab);      // step 4
        sq_mid   <<<blkM, tpb>>>(Ab, Bb);      // step 5
        sq_last  <<<blkQ, tpb>>>(Bb, ob);      // step 6: interleaved -> planar
    }
}